// round 2
// baseline (speedup 1.0000x reference)
#include <cuda_runtime.h>
#include <cstdint>
#include <cstddef>

// Problem constants
#define BB   64
#define SS   512
#define DD   512
#define HH   8
#define LL   4
#define DKK  64
#define DFFC 2048
#define NSKC 300
#define FC1C 512
#define FC2C 256
#define NTOK (BB * SS)        // 32768
#define FFN_CHUNK 8192        // rows per FFN chunk (h1 slice = 67MB, fits L2)

// ---------------- scratch (static device globals; no allocation allowed) ----
__device__ float g_x  [NTOK * DD];
__device__ float g_y  [NTOK * DD];
__device__ float g_qe [NTOK * DD];
__device__ float g_k  [NTOK * DD];   // reused as head hidden A (32768x512)
__device__ float g_v  [NTOK * DD];   // reused as head hidden B (32768x256)
__device__ float g_o  [NTOK * DD];
__device__ float g_tmp[NTOK * DD];
__device__ float g_h1 [FFN_CHUNK * DFFC];   // FFN hidden slice, reused per chunk

// ---------------- embedding: x = qe + pe ; y = qa + qe + pe ----------------
__global__ void embed_kernel(const int* __restrict__ qd, const int* __restrict__ tg,
                             const float* __restrict__ pe, const float* __restrict__ qemb,
                             const float* __restrict__ qaemb,
                             float* __restrict__ x, float* __restrict__ y,
                             float* __restrict__ qe) {
    int t = blockIdx.x;                 // token index (b*S + s)
    int s = t & (SS - 1);
    int qi = qd[t];
    int ti = tg[t];
    int c = threadIdx.x << 2;           // 128 threads * 4 floats = 512
    float4 qv = *(const float4*)(qemb + (size_t)qi * DD + c);
    float4 pv = *(const float4*)(pe   + (size_t)s  * DD + c);
    float4 av = *(const float4*)(qaemb + (size_t)ti * DD + c);
    float4 xv = make_float4(qv.x + pv.x, qv.y + pv.y, qv.z + pv.z, qv.w + pv.w);
    float4 yv = make_float4(av.x + xv.x, av.y + xv.y, av.z + xv.z, av.w + xv.w);
    *(float4*)(qe + (size_t)t * DD + c) = qv;
    *(float4*)(x  + (size_t)t * DD + c) = xv;
    *(float4*)(y  + (size_t)t * DD + c) = yv;
}

// ---------------- tiled fp32 SGEMM: C = A(+A2 concat) @ B + bias [,ReLU] ----
// 128x128 block tile, BK=16, 256 threads, 8x8 per thread.
template<int RELU, bool GN, bool DUAL>
__global__ __launch_bounds__(256)
void sgemm(const float* __restrict__ A, const float* __restrict__ A2,
           const float* __restrict__ Bm, const float* __restrict__ bias,
           float* __restrict__ C, int N, int K) {
    __shared__ float As[16][128];
    __shared__ float Bs[16][128];
    const int tid  = threadIdx.x;
    const int tx   = tid & 15;
    const int ty   = tid >> 4;
    const int row0 = blockIdx.y << 7;
    const int col0 = blockIdx.x << 7;
    const int arow = tid >> 2;
    const int acol = (tid & 3) << 2;
    const int brow = tid >> 5;
    const int bcol = (tid & 31) << 2;
    const int HK   = K >> 1;

    float acc[8][8];
#pragma unroll
    for (int i = 0; i < 8; i++)
#pragma unroll
        for (int j = 0; j < 8; j++) acc[i][j] = 0.f;

    for (int k0 = 0; k0 < K; k0 += 16) {
#pragma unroll
        for (int p = 0; p < 2; p++) {
            int r  = arow + (p << 6);
            int gk = k0 + acol;
            float4 av;
            if (DUAL) {
                const float* src = (gk < HK)
                    ? (A  + (size_t)(row0 + r) * HK + gk)
                    : (A2 + (size_t)(row0 + r) * HK + (gk - HK));
                av = *(const float4*)src;
            } else {
                av = *(const float4*)(A + (size_t)(row0 + r) * K + gk);
            }
            As[acol + 0][r] = av.x;
            As[acol + 1][r] = av.y;
            As[acol + 2][r] = av.z;
            As[acol + 3][r] = av.w;

            int rb  = brow + (p << 3);
            int gkB = k0 + rb;
            int gc  = col0 + bcol;
            float4 bv;
            if (GN) {
                const float* bp = Bm + (size_t)gkB * N;
                bv.x = (gc + 0 < N) ? bp[gc + 0] : 0.f;
                bv.y = (gc + 1 < N) ? bp[gc + 1] : 0.f;
                bv.z = (gc + 2 < N) ? bp[gc + 2] : 0.f;
                bv.w = (gc + 3 < N) ? bp[gc + 3] : 0.f;
            } else {
                bv = *(const float4*)(Bm + (size_t)gkB * N + gc);
            }
            *(float4*)&Bs[rb][bcol] = bv;
        }
        __syncthreads();
#pragma unroll
        for (int kk = 0; kk < 16; kk++) {
            float4 a0 = *(const float4*)&As[kk][(ty << 2)];
            float4 a1 = *(const float4*)&As[kk][64 + (ty << 2)];
            float4 b0 = *(const float4*)&Bs[kk][(tx << 2)];
            float4 b1 = *(const float4*)&Bs[kk][64 + (tx << 2)];
            float a[8]  = {a0.x, a0.y, a0.z, a0.w, a1.x, a1.y, a1.z, a1.w};
            float bb[8] = {b0.x, b0.y, b0.z, b0.w, b1.x, b1.y, b1.z, b1.w};
#pragma unroll
            for (int i = 0; i < 8; i++)
#pragma unroll
                for (int j = 0; j < 8; j++)
                    acc[i][j] = fmaf(a[i], bb[j], acc[i][j]);
        }
        __syncthreads();
    }

    // epilogue
#pragma unroll
    for (int i = 0; i < 8; i++) {
        int rl = (i < 4) ? ((ty << 2) + i) : (64 + (ty << 2) + i - 4);
        int r  = row0 + rl;
        if (GN) {
#pragma unroll
            for (int j = 0; j < 8; j++) {
                int c = col0 + ((j < 4) ? ((tx << 2) + j) : (64 + (tx << 2) + j - 4));
                if (c < N) {
                    float v = acc[i][j] + bias[c];
                    if (RELU) v = fmaxf(v, 0.f);
                    C[(size_t)r * N + c] = v;
                }
            }
        } else {
            float4 bv0 = *(const float4*)(bias + col0 + (tx << 2));
            float4 bv1 = *(const float4*)(bias + col0 + 64 + (tx << 2));
            float4 v0 = make_float4(acc[i][0] + bv0.x, acc[i][1] + bv0.y,
                                    acc[i][2] + bv0.z, acc[i][3] + bv0.w);
            float4 v1 = make_float4(acc[i][4] + bv1.x, acc[i][5] + bv1.y,
                                    acc[i][6] + bv1.z, acc[i][7] + bv1.w);
            if (RELU) {
                v0.x = fmaxf(v0.x, 0.f); v0.y = fmaxf(v0.y, 0.f);
                v0.z = fmaxf(v0.z, 0.f); v0.w = fmaxf(v0.w, 0.f);
                v1.x = fmaxf(v1.x, 0.f); v1.y = fmaxf(v1.y, 0.f);
                v1.z = fmaxf(v1.z, 0.f); v1.w = fmaxf(v1.w, 0.f);
            }
            *(float4*)(C + (size_t)r * N + col0 + (tx << 2))      = v0;
            *(float4*)(C + (size_t)r * N + col0 + 64 + (tx << 2)) = v1;
        }
    }
}

// ---------------- flash-style causal attention (q == k, strict j < i) ------
// One block per (i-tile, head, batch). 64 query rows, dk=64, 256 threads.
#define SPAD 68
__global__ __launch_bounds__(256)
void attn_kernel(const float* __restrict__ Kt, const float* __restrict__ Vt,
                 float* __restrict__ Ot) {
    extern __shared__ float sm[];
    float* Qs = sm;                 // [64][SPAD]
    float* Ks = sm + 64 * SPAD;     // reused for P after scores
    float* Vs = sm + 2 * 64 * SPAD;

    const int it = blockIdx.x;
    const int h  = blockIdx.y;
    const int b  = blockIdx.z;
    const int tid = threadIdx.x;
    const int tx = tid & 15;
    const int ty = tid >> 4;
    const int lr = tid >> 4;          // load row 0..15
    const int lc = (tid & 15) << 2;   // load col (x4)

    const float* Kb = Kt + ((size_t)b * SS) * DD + h * 64;
    const float* Vb = Vt + ((size_t)b * SS) * DD + h * 64;

    // Q tile (rows it*64 ..)
#pragma unroll
    for (int p = 0; p < 4; p++) {
        int r = lr + (p << 4);
        float4 t4 = *(const float4*)(Kb + (size_t)(it * 64 + r) * DD + lc);
        Qs[r * SPAD + lc + 0] = t4.x; Qs[r * SPAD + lc + 1] = t4.y;
        Qs[r * SPAD + lc + 2] = t4.z; Qs[r * SPAD + lc + 3] = t4.w;
    }

    float m[4], l[4], oa[4][4];
#pragma unroll
    for (int i = 0; i < 4; i++) {
        m[i] = -1e30f; l[i] = 0.f;
        oa[i][0] = oa[i][1] = oa[i][2] = oa[i][3] = 0.f;
    }

    for (int jt = 0; jt <= it; jt++) {
        __syncthreads();   // previous P/V reads done before overwriting
#pragma unroll
        for (int p = 0; p < 4; p++) {
            int r = lr + (p << 4);
            float4 t4 = *(const float4*)(Kb + (size_t)(jt * 64 + r) * DD + lc);
            Ks[r * SPAD + lc + 0] = t4.x; Ks[r * SPAD + lc + 1] = t4.y;
            Ks[r * SPAD + lc + 2] = t4.z; Ks[r * SPAD + lc + 3] = t4.w;
            float4 u4 = *(const float4*)(Vb + (size_t)(jt * 64 + r) * DD + lc);
            Vs[r * SPAD + lc + 0] = u4.x; Vs[r * SPAD + lc + 1] = u4.y;
            Vs[r * SPAD + lc + 2] = u4.z; Vs[r * SPAD + lc + 3] = u4.w;
        }
        __syncthreads();

        // scores: 4x4 per thread over 64-dim
        float sc[4][4];
#pragma unroll
        for (int i = 0; i < 4; i++)
#pragma unroll
            for (int j = 0; j < 4; j++) sc[i][j] = 0.f;
#pragma unroll
        for (int kk = 0; kk < 64; kk += 4) {
            float4 q[4], kv[4];
#pragma unroll
            for (int i = 0; i < 4; i++)
                q[i] = *(const float4*)&Qs[((ty << 2) + i) * SPAD + kk];
#pragma unroll
            for (int j = 0; j < 4; j++)
                kv[j] = *(const float4*)&Ks[((tx << 2) + j) * SPAD + kk];
#pragma unroll
            for (int i = 0; i < 4; i++)
#pragma unroll
                for (int j = 0; j < 4; j++)
                    sc[i][j] += q[i].x * kv[j].x + q[i].y * kv[j].y +
                                q[i].z * kv[j].z + q[i].w * kv[j].w;
        }

        float p[4][4];
        const bool diag = (jt == it);
#pragma unroll
        for (int i = 0; i < 4; i++) {
            int ig = it * 64 + (ty << 2) + i;
            float rmax = -1e30f;
#pragma unroll
            for (int j = 0; j < 4; j++) {
                float v = sc[i][j] * 0.125f;           // 1/sqrt(64)
                if (diag) {
                    int jg = jt * 64 + (tx << 2) + j;
                    if (jg >= ig) v = -1e30f;
                }
                sc[i][j] = v;
                rmax = fmaxf(rmax, v);
            }
#pragma unroll
            for (int off = 8; off; off >>= 1)
                rmax = fmaxf(rmax, __shfl_xor_sync(0xffffffffu, rmax, off));
            float nm  = fmaxf(m[i], rmax);
            float fac = __expf(m[i] - nm);
            float rs  = 0.f;
#pragma unroll
            for (int j = 0; j < 4; j++) {
                float pv = __expf(sc[i][j] - nm);
                p[i][j] = pv;
                rs += pv;
            }
#pragma unroll
            for (int off = 8; off; off >>= 1)
                rs += __shfl_xor_sync(0xffffffffu, rs, off);
            l[i] = l[i] * fac + rs;
            oa[i][0] *= fac; oa[i][1] *= fac; oa[i][2] *= fac; oa[i][3] *= fac;
            m[i] = nm;
        }

        __syncthreads();   // all threads done reading Ks (scores)
#pragma unroll
        for (int i = 0; i < 4; i++)
#pragma unroll
            for (int j = 0; j < 4; j++)
                Ks[((ty << 2) + i) * SPAD + (tx << 2) + j] = p[i][j];
        __syncthreads();

        // O += P @ V
#pragma unroll
        for (int j = 0; j < 64; j++) {
            float4 vv = *(const float4*)&Vs[j * SPAD + (tx << 2)];
#pragma unroll
            for (int i = 0; i < 4; i++) {
                float pv = Ks[((ty << 2) + i) * SPAD + j];
                oa[i][0] += pv * vv.x; oa[i][1] += pv * vv.y;
                oa[i][2] += pv * vv.z; oa[i][3] += pv * vv.w;
            }
        }
    }

    // store (row_keep: zero seq position 0)
#pragma unroll
    for (int i = 0; i < 4; i++) {
        int r  = (ty << 2) + i;
        int ig = it * 64 + r;
        float inv = (ig == 0 || l[i] <= 0.f) ? 0.f : 1.f / l[i];
        float4 ov = make_float4(oa[i][0] * inv, oa[i][1] * inv,
                                oa[i][2] * inv, oa[i][3] * inv);
        *(float4*)(Ot + ((size_t)b * SS + ig) * DD + h * 64 + (tx << 2)) = ov;
    }
}

// ---------------- residual + LayerNorm: x = LN(x + r) * g + b ---------------
__global__ __launch_bounds__(128)
void add_ln_kernel(float* __restrict__ x, const float* __restrict__ r,
                   const float* __restrict__ g, const float* __restrict__ b) {
    int t = blockIdx.x;
    int c = threadIdx.x << 2;
    float4 xv = *(const float4*)(x + (size_t)t * DD + c);
    float4 rv = *(const float4*)(r + (size_t)t * DD + c);
    float4 v = make_float4(xv.x + rv.x, xv.y + rv.y, xv.z + rv.z, xv.w + rv.w);
    float s  = v.x + v.y + v.z + v.w;
    float ss = v.x * v.x + v.y * v.y + v.z * v.z + v.w * v.w;
#pragma unroll
    for (int off = 16; off; off >>= 1) {
        s  += __shfl_xor_sync(0xffffffffu, s,  off);
        ss += __shfl_xor_sync(0xffffffffu, ss, off);
    }
    __shared__ float sh[8];
    int w = threadIdx.x >> 5;
    if ((threadIdx.x & 31) == 0) { sh[w] = s; sh[4 + w] = ss; }
    __syncthreads();
    s  = sh[0] + sh[1] + sh[2] + sh[3];
    ss = sh[4] + sh[5] + sh[6] + sh[7];
    float mean = s * (1.f / DD);
    float var  = ss * (1.f / DD) - mean * mean;
    float rstd = rsqrtf(var + 1e-5f);
    float4 gv = *(const float4*)(g + c);
    float4 bv = *(const float4*)(b + c);
    float4 ov = make_float4((v.x - mean) * rstd * gv.x + bv.x,
                            (v.y - mean) * rstd * gv.y + bv.y,
                            (v.z - mean) * rstd * gv.z + bv.z,
                            (v.w - mean) * rstd * gv.w + bv.w);
    *(float4*)(x + (size_t)t * DD + c) = ov;
}

// ---------------- host driver ----------------------------------------------
extern "C" void kernel_launch(void* const* d_in, const int* in_sizes, int n_in,
                              void* d_out, int out_size) {
    const int*   q_data = (const int*)d_in[0];
    const int*   target = (const int*)d_in[1];
    const float* pe     = (const float*)d_in[2];
    const float* q_emb  = (const float*)d_in[3];
    const float* qa_emb = (const float*)d_in[4];
    const float* Wk     = (const float*)d_in[5];
    const float* bk     = (const float*)d_in[6];
    const float* Wv     = (const float*)d_in[7];
    const float* bv     = (const float*)d_in[8];
    const float* Wo     = (const float*)d_in[9];
    const float* bo     = (const float*)d_in[10];
    const float* ln1_g  = (const float*)d_in[11];
    const float* ln1_b  = (const float*)d_in[12];
    const float* W1     = (const float*)d_in[13];
    const float* b1     = (const float*)d_in[14];
    const float* W2     = (const float*)d_in[15];
    const float* b2     = (const float*)d_in[16];
    const float* ln2_g  = (const float*)d_in[17];
    const float* ln2_b  = (const float*)d_in[18];
    const float* Wout1  = (const float*)d_in[19];
    const float* bout1  = (const float*)d_in[20];
    const float* Wout2  = (const float*)d_in[21];
    const float* bout2  = (const float*)d_in[22];
    const float* Wout3  = (const float*)d_in[23];
    const float* bout3  = (const float*)d_in[24];
    float* out = (float*)d_out;

    float *x, *y, *qe, *k, *v, *o, *tmp, *h1;
    cudaGetSymbolAddress((void**)&x,   g_x);
    cudaGetSymbolAddress((void**)&y,   g_y);
    cudaGetSymbolAddress((void**)&qe,  g_qe);
    cudaGetSymbolAddress((void**)&k,   g_k);
    cudaGetSymbolAddress((void**)&v,   g_v);
    cudaGetSymbolAddress((void**)&o,   g_o);
    cudaGetSymbolAddress((void**)&tmp, g_tmp);
    cudaGetSymbolAddress((void**)&h1,  g_h1);

    const int attn_smem = 3 * 64 * SPAD * (int)sizeof(float);
    cudaFuncSetAttribute(attn_kernel, cudaFuncAttributeMaxDynamicSharedMemorySize,
                         attn_smem);

    embed_kernel<<<NTOK, 128>>>(q_data, target, pe, q_emb, qa_emb, x, y, qe);

    for (int l = 0; l < LL; l++) {
        const float* Wk_l = Wk + (size_t)l * DD * DD;
        const float* bk_l = bk + (size_t)l * DD;
        const float* Wv_l = Wv + (size_t)l * DD * DD;
        const float* bv_l = bv + (size_t)l * DD;
        const float* Wo_l = Wo + (size_t)l * DD * DD;
        const float* bo_l = bo + (size_t)l * DD;
        const float* W1_l = W1 + (size_t)l * DD * DFFC;
        const float* b1_l = b1 + (size_t)l * DFFC;
        const float* W2_l = W2 + (size_t)l * DFFC * DD;
        const float* b2_l = b2 + (size_t)l * DD;

        // k = x @ Wk + bk  (serves as both q and k: kq_same=1)
        sgemm<0, false, false><<<dim3(DD / 128, NTOK / 128), 256>>>(
            x, nullptr, Wk_l, bk_l, k, DD, DD);
        // v = y @ Wv + bv
        sgemm<0, false, false><<<dim3(DD / 128, NTOK / 128), 256>>>(
            y, nullptr, Wv_l, bv_l, v, DD, DD);
        // attention -> o
        attn_kernel<<<dim3(SS / 64, HH, BB), 256, attn_smem>>>(k, v, o);
        // tmp = o @ Wo + bo
        sgemm<0, false, false><<<dim3(DD / 128, NTOK / 128), 256>>>(
            o, nullptr, Wo_l, bo_l, tmp, DD, DD);
        // x = LN(x + tmp)
        add_ln_kernel<<<NTOK, 128>>>(x, tmp, ln1_g + (size_t)l * DD,
                                     ln1_b + (size_t)l * DD);
        // FFN, chunked over M so h1 slice stays L2-resident
        for (int c = 0; c < NTOK / FFN_CHUNK; c++) {
            const float* xc = x   + (size_t)c * FFN_CHUNK * DD;
            float*       tc = tmp + (size_t)c * FFN_CHUNK * DD;
            sgemm<1, false, false><<<dim3(DFFC / 128, FFN_CHUNK / 128), 256>>>(
                xc, nullptr, W1_l, b1_l, h1, DFFC, DD);
            sgemm<0, false, false><<<dim3(DD / 128, FFN_CHUNK / 128), 256>>>(
                h1, nullptr, W2_l, b2_l, tc, DD, DFFC);
        }
        // x = LN(x + tmp)
        add_ln_kernel<<<NTOK, 128>>>(x, tmp, ln2_g + (size_t)l * DD,
                                     ln2_b + (size_t)l * DD);
    }

    // head: hA = relu(concat(x, qe) @ Wout1 + bout1)   (dual-A fused concat)
    sgemm<1, false, true><<<dim3(FC1C / 128, NTOK / 128), 256>>>(
        x, qe, Wout1, bout1, k, FC1C, 2 * DD);
    // hB = relu(hA @ Wout2 + bout2)
    sgemm<1, false, false><<<dim3(FC2C / 128, NTOK / 128), 256>>>(
        k, nullptr, Wout2, bout2, v, FC2C, FC1C);
    // out = hB @ Wout3 + bout3   (N=300, guarded)
    sgemm<0, true, false><<<dim3((NSKC + 127) / 128, NTOK / 128), 256>>>(
        v, nullptr, Wout3, bout3, out, NSKC, FC2C);
}

// round 3
// speedup vs baseline: 1.9659x; 1.9659x over previous
#include <cuda_runtime.h>
#include <cstdint>
#include <cstddef>

// Problem constants
#define BB   64
#define SS   512
#define DD   512
#define HH   8
#define LL   4
#define DFFC 2048
#define NSKC 300
#define FC1C 512
#define FC2C 256
#define NTOK (BB * SS)        // 32768
#define FFN_CHUNK 8192

// ---------------- scratch ---------------------------------------------------
__device__ float g_x  [NTOK * DD];
__device__ float g_y  [NTOK * DD];
__device__ float g_qe [NTOK * DD];
__device__ float g_k  [NTOK * DD];
__device__ float g_v  [NTOK * DD];
__device__ float g_o  [NTOK * DD];
__device__ float g_tmp[NTOK * DD];
__device__ float g_h1 [FFN_CHUNK * DFFC];

// ---------------- embedding -------------------------------------------------
__global__ void embed_kernel(const int* __restrict__ qd, const int* __restrict__ tg,
                             const float* __restrict__ pe, const float* __restrict__ qemb,
                             const float* __restrict__ qaemb,
                             float* __restrict__ x, float* __restrict__ y,
                             float* __restrict__ qe) {
    int t = blockIdx.x;
    int s = t & (SS - 1);
    int qi = qd[t];
    int ti = tg[t];
    int c = threadIdx.x << 2;
    float4 qv = *(const float4*)(qemb + (size_t)qi * DD + c);
    float4 pv = *(const float4*)(pe   + (size_t)s  * DD + c);
    float4 av = *(const float4*)(qaemb + (size_t)ti * DD + c);
    float4 xv = make_float4(qv.x + pv.x, qv.y + pv.y, qv.z + pv.z, qv.w + pv.w);
    float4 yv = make_float4(av.x + xv.x, av.y + xv.y, av.z + xv.z, av.w + xv.w);
    *(float4*)(qe + (size_t)t * DD + c) = qv;
    *(float4*)(x  + (size_t)t * DD + c) = xv;
    *(float4*)(y  + (size_t)t * DD + c) = yv;
}

// ---------------- tf32 tensor-core GEMM ------------------------------------
// C[M,N] = A[M,K] (optionally concat A|A2) @ B[K,N] + bias, optional ReLU.
// 128x128x16 tile, 256 thr, 8 warps (2x4), warp tile 64x32, mma.m16n8k8.tf32.
#define SA 20    // As row stride (floats): conflict-free for frag loads
#define SB 136   // Bs row stride

__device__ __forceinline__ void cp16(uint32_t dst, const void* src) {
    asm volatile("cp.async.cg.shared.global [%0], [%1], 16;" :: "r"(dst), "l"(src) : "memory");
}
__device__ __forceinline__ void cp16z(uint32_t dst, const void* src, int bytes) {
    asm volatile("cp.async.cg.shared.global [%0], [%1], 16, %2;"
                 :: "r"(dst), "l"(src), "r"(bytes) : "memory");
}
__device__ __forceinline__ uint32_t tf32(float x) {
    uint32_t r;
    asm("cvt.rna.tf32.f32 %0, %1;" : "=r"(r) : "f"(x));
    return r;
}

template<int RELU, bool GN, bool DUAL>
__global__ __launch_bounds__(256, 2)
void tgemm(const float* __restrict__ A, const float* __restrict__ A2,
           const float* __restrict__ Bm, const float* __restrict__ bias,
           float* __restrict__ C, int N, int K) {
    __shared__ float As[2][128 * SA];
    __shared__ float Bs[2][16 * SB];

    const int tid  = threadIdx.x;
    const int lane = tid & 31;
    const int warp = tid >> 5;
    const int g    = lane >> 2;      // group id (0..7)
    const int tig  = lane & 3;       // thread in group (0..3)
    const int wm   = (warp >> 2) * 64;
    const int wn   = (warp & 3) * 32;
    const int row0 = blockIdx.y << 7;
    const int col0 = blockIdx.x << 7;
    const int HK   = K >> 1;

    // cp.async thread mapping
    const int ar = tid >> 1;                 // A row 0..127
    const int ac = (tid & 1) << 1;           // A chunk base (of 4 x 16B)
    const int br = tid >> 4;                 // B row 0..15
    const int bc = (tid & 15) << 1;          // B chunk base (of 32 x 16B)

    const uint32_t asBase = (uint32_t)__cvta_generic_to_shared(&As[0][0]);
    const uint32_t bsBase = (uint32_t)__cvta_generic_to_shared(&Bs[0][0]);
    const uint32_t asStep = 128 * SA * 4;
    const uint32_t bsStep = 16 * SB * 4;

    float acc[4][4][4];
#pragma unroll
    for (int i = 0; i < 4; i++)
#pragma unroll
        for (int j = 0; j < 4; j++) {
            acc[i][j][0] = acc[i][j][1] = acc[i][j][2] = acc[i][j][3] = 0.f;
        }

    auto load_tiles = [&](int buf, int k0) {
        uint32_t ad = asBase + buf * asStep + (uint32_t)(ar * (SA * 4)) + ac * 16;
#pragma unroll
        for (int j = 0; j < 2; j++) {
            int gk = k0 + (ac + j) * 4;
            const float* src;
            if (DUAL) {
                src = (gk < HK) ? (A  + (size_t)(row0 + ar) * HK + gk)
                                : (A2 + (size_t)(row0 + ar) * HK + (gk - HK));
            } else {
                src = A + (size_t)(row0 + ar) * K + gk;
            }
            cp16(ad + j * 16, src);
        }
        uint32_t bd = bsBase + buf * bsStep + (uint32_t)(br * (SB * 4)) + bc * 16;
#pragma unroll
        for (int j = 0; j < 2; j++) {
            int gc = col0 + (bc + j) * 4;
            if (GN) {
                int bytes = (N - gc) * 4;
                bytes = bytes < 0 ? 0 : (bytes > 16 ? 16 : bytes);
                const float* src = Bm + (size_t)(k0 + br) * N + (gc < N ? gc : 0);
                cp16z(bd + j * 16, src, bytes);
            } else {
                cp16(bd + j * 16, Bm + (size_t)(k0 + br) * N + gc);
            }
        }
    };

    const int iters = K >> 4;
    load_tiles(0, 0);
    asm volatile("cp.async.commit_group;" ::: "memory");

    int buf = 0;
    for (int it = 0; it < iters; it++) {
        asm volatile("cp.async.wait_group 0;" ::: "memory");
        __syncthreads();
        if (it + 1 < iters) {
            load_tiles(buf ^ 1, (it + 1) << 4);
            asm volatile("cp.async.commit_group;" ::: "memory");
        }
        const float* as = As[buf];
        const float* bs = Bs[buf];
#pragma unroll
        for (int ks = 0; ks < 2; ks++) {
            const int kk = ks << 3;
            uint32_t bfr[4][2];
#pragma unroll
            for (int nf = 0; nf < 4; nf++) {
                int nn = wn + nf * 8 + g;
                bfr[nf][0] = tf32(bs[(kk + tig) * SB + nn]);
                bfr[nf][1] = tf32(bs[(kk + tig + 4) * SB + nn]);
            }
#pragma unroll
            for (int mf = 0; mf < 4; mf++) {
                int mm = wm + mf * 16 + g;
                uint32_t a0 = tf32(as[mm * SA + kk + tig]);
                uint32_t a1 = tf32(as[(mm + 8) * SA + kk + tig]);
                uint32_t a2 = tf32(as[mm * SA + kk + tig + 4]);
                uint32_t a3 = tf32(as[(mm + 8) * SA + kk + tig + 4]);
#pragma unroll
                for (int nf = 0; nf < 4; nf++) {
                    asm volatile(
                        "mma.sync.aligned.m16n8k8.row.col.f32.tf32.tf32.f32 "
                        "{%0,%1,%2,%3}, {%4,%5,%6,%7}, {%8,%9}, {%0,%1,%2,%3};"
                        : "+f"(acc[mf][nf][0]), "+f"(acc[mf][nf][1]),
                          "+f"(acc[mf][nf][2]), "+f"(acc[mf][nf][3])
                        : "r"(a0), "r"(a1), "r"(a2), "r"(a3),
                          "r"(bfr[nf][0]), "r"(bfr[nf][1]));
                }
            }
        }
        buf ^= 1;
    }

    // epilogue
#pragma unroll
    for (int mf = 0; mf < 4; mf++) {
        int r = row0 + wm + mf * 16 + g;
#pragma unroll
        for (int nf = 0; nf < 4; nf++) {
            int cc = col0 + wn + nf * 8 + tig * 2;
            if (GN) {
#pragma unroll
                for (int q = 0; q < 4; q++) {
                    int rr = r + (q >> 1) * 8;
                    int c2 = cc + (q & 1);
                    if (c2 < N) {
                        float v = acc[mf][nf][q] + bias[c2];
                        if (RELU) v = fmaxf(v, 0.f);
                        C[(size_t)rr * N + c2] = v;
                    }
                }
            } else {
                float b0 = bias[cc], b1 = bias[cc + 1];
                float2 v0 = make_float2(acc[mf][nf][0] + b0, acc[mf][nf][1] + b1);
                float2 v1 = make_float2(acc[mf][nf][2] + b0, acc[mf][nf][3] + b1);
                if (RELU) {
                    v0.x = fmaxf(v0.x, 0.f); v0.y = fmaxf(v0.y, 0.f);
                    v1.x = fmaxf(v1.x, 0.f); v1.y = fmaxf(v1.y, 0.f);
                }
                *(float2*)(C + (size_t)r * N + cc)       = v0;
                *(float2*)(C + (size_t)(r + 8) * N + cc) = v1;
            }
        }
    }
}

// ---------------- flash-style causal attention (unchanged) ------------------
#define SPAD 68
__global__ __launch_bounds__(256)
void attn_kernel(const float* __restrict__ Kt, const float* __restrict__ Vt,
                 float* __restrict__ Ot) {
    extern __shared__ float sm[];
    float* Qs = sm;
    float* Ks = sm + 64 * SPAD;
    float* Vs = sm + 2 * 64 * SPAD;

    const int it = blockIdx.x;
    const int h  = blockIdx.y;
    const int b  = blockIdx.z;
    const int tid = threadIdx.x;
    const int tx = tid & 15;
    const int ty = tid >> 4;
    const int lr = tid >> 4;
    const int lc = (tid & 15) << 2;

    const float* Kb = Kt + ((size_t)b * SS) * DD + h * 64;
    const float* Vb = Vt + ((size_t)b * SS) * DD + h * 64;

#pragma unroll
    for (int p = 0; p < 4; p++) {
        int r = lr + (p << 4);
        float4 t4 = *(const float4*)(Kb + (size_t)(it * 64 + r) * DD + lc);
        Qs[r * SPAD + lc + 0] = t4.x; Qs[r * SPAD + lc + 1] = t4.y;
        Qs[r * SPAD + lc + 2] = t4.z; Qs[r * SPAD + lc + 3] = t4.w;
    }

    float m[4], l[4], oa[4][4];
#pragma unroll
    for (int i = 0; i < 4; i++) {
        m[i] = -1e30f; l[i] = 0.f;
        oa[i][0] = oa[i][1] = oa[i][2] = oa[i][3] = 0.f;
    }

    for (int jt = 0; jt <= it; jt++) {
        __syncthreads();
#pragma unroll
        for (int p = 0; p < 4; p++) {
            int r = lr + (p << 4);
            float4 t4 = *(const float4*)(Kb + (size_t)(jt * 64 + r) * DD + lc);
            Ks[r * SPAD + lc + 0] = t4.x; Ks[r * SPAD + lc + 1] = t4.y;
            Ks[r * SPAD + lc + 2] = t4.z; Ks[r * SPAD + lc + 3] = t4.w;
            float4 u4 = *(const float4*)(Vb + (size_t)(jt * 64 + r) * DD + lc);
            Vs[r * SPAD + lc + 0] = u4.x; Vs[r * SPAD + lc + 1] = u4.y;
            Vs[r * SPAD + lc + 2] = u4.z; Vs[r * SPAD + lc + 3] = u4.w;
        }
        __syncthreads();

        float sc[4][4];
#pragma unroll
        for (int i = 0; i < 4; i++)
#pragma unroll
            for (int j = 0; j < 4; j++) sc[i][j] = 0.f;
#pragma unroll
        for (int kk = 0; kk < 64; kk += 4) {
            float4 q[4], kv[4];
#pragma unroll
            for (int i = 0; i < 4; i++)
                q[i] = *(const float4*)&Qs[((ty << 2) + i) * SPAD + kk];
#pragma unroll
            for (int j = 0; j < 4; j++)
                kv[j] = *(const float4*)&Ks[((tx << 2) + j) * SPAD + kk];
#pragma unroll
            for (int i = 0; i < 4; i++)
#pragma unroll
                for (int j = 0; j < 4; j++)
                    sc[i][j] += q[i].x * kv[j].x + q[i].y * kv[j].y +
                                q[i].z * kv[j].z + q[i].w * kv[j].w;
        }

        float p[4][4];
        const bool diag = (jt == it);
#pragma unroll
        for (int i = 0; i < 4; i++) {
            int ig = it * 64 + (ty << 2) + i;
            float rmax = -1e30f;
#pragma unroll
            for (int j = 0; j < 4; j++) {
                float v = sc[i][j] * 0.125f;
                if (diag) {
                    int jg = jt * 64 + (tx << 2) + j;
                    if (jg >= ig) v = -1e30f;
                }
                sc[i][j] = v;
                rmax = fmaxf(rmax, v);
            }
#pragma unroll
            for (int off = 8; off; off >>= 1)
                rmax = fmaxf(rmax, __shfl_xor_sync(0xffffffffu, rmax, off));
            float nm  = fmaxf(m[i], rmax);
            float fac = __expf(m[i] - nm);
            float rs  = 0.f;
#pragma unroll
            for (int j = 0; j < 4; j++) {
                float pv = __expf(sc[i][j] - nm);
                p[i][j] = pv;
                rs += pv;
            }
#pragma unroll
            for (int off = 8; off; off >>= 1)
                rs += __shfl_xor_sync(0xffffffffu, rs, off);
            l[i] = l[i] * fac + rs;
            oa[i][0] *= fac; oa[i][1] *= fac; oa[i][2] *= fac; oa[i][3] *= fac;
            m[i] = nm;
        }

        __syncthreads();
#pragma unroll
        for (int i = 0; i < 4; i++)
#pragma unroll
            for (int j = 0; j < 4; j++)
                Ks[((ty << 2) + i) * SPAD + (tx << 2) + j] = p[i][j];
        __syncthreads();

#pragma unroll
        for (int j = 0; j < 64; j++) {
            float4 vv = *(const float4*)&Vs[j * SPAD + (tx << 2)];
#pragma unroll
            for (int i = 0; i < 4; i++) {
                float pv = Ks[((ty << 2) + i) * SPAD + j];
                oa[i][0] += pv * vv.x; oa[i][1] += pv * vv.y;
                oa[i][2] += pv * vv.z; oa[i][3] += pv * vv.w;
            }
        }
    }

#pragma unroll
    for (int i = 0; i < 4; i++) {
        int r  = (ty << 2) + i;
        int ig = it * 64 + r;
        float inv = (ig == 0 || l[i] <= 0.f) ? 0.f : 1.f / l[i];
        float4 ov = make_float4(oa[i][0] * inv, oa[i][1] * inv,
                                oa[i][2] * inv, oa[i][3] * inv);
        *(float4*)(Ot + ((size_t)b * SS + ig) * DD + h * 64 + (tx << 2)) = ov;
    }
}

// ---------------- residual + LayerNorm --------------------------------------
__global__ __launch_bounds__(128)
void add_ln_kernel(float* __restrict__ x, const float* __restrict__ r,
                   const float* __restrict__ g, const float* __restrict__ b) {
    int t = blockIdx.x;
    int c = threadIdx.x << 2;
    float4 xv = *(const float4*)(x + (size_t)t * DD + c);
    float4 rv = *(const float4*)(r + (size_t)t * DD + c);
    float4 v = make_float4(xv.x + rv.x, xv.y + rv.y, xv.z + rv.z, xv.w + rv.w);
    float s  = v.x + v.y + v.z + v.w;
    float ss = v.x * v.x + v.y * v.y + v.z * v.z + v.w * v.w;
#pragma unroll
    for (int off = 16; off; off >>= 1) {
        s  += __shfl_xor_sync(0xffffffffu, s,  off);
        ss += __shfl_xor_sync(0xffffffffu, ss, off);
    }
    __shared__ float sh[8];
    int w = threadIdx.x >> 5;
    if ((threadIdx.x & 31) == 0) { sh[w] = s; sh[4 + w] = ss; }
    __syncthreads();
    s  = sh[0] + sh[1] + sh[2] + sh[3];
    ss = sh[4] + sh[5] + sh[6] + sh[7];
    float mean = s * (1.f / DD);
    float var  = ss * (1.f / DD) - mean * mean;
    float rstd = rsqrtf(var + 1e-5f);
    float4 gv = *(const float4*)(g + c);
    float4 bv = *(const float4*)(b + c);
    float4 ov = make_float4((v.x - mean) * rstd * gv.x + bv.x,
                            (v.y - mean) * rstd * gv.y + bv.y,
                            (v.z - mean) * rstd * gv.z + bv.z,
                            (v.w - mean) * rstd * gv.w + bv.w);
    *(float4*)(x + (size_t)t * DD + c) = ov;
}

// ---------------- host driver ----------------------------------------------
extern "C" void kernel_launch(void* const* d_in, const int* in_sizes, int n_in,
                              void* d_out, int out_size) {
    const int*   q_data = (const int*)d_in[0];
    const int*   target = (const int*)d_in[1];
    const float* pe     = (const float*)d_in[2];
    const float* q_emb  = (const float*)d_in[3];
    const float* qa_emb = (const float*)d_in[4];
    const float* Wk     = (const float*)d_in[5];
    const float* bk     = (const float*)d_in[6];
    const float* Wv     = (const float*)d_in[7];
    const float* bv     = (const float*)d_in[8];
    const float* Wo     = (const float*)d_in[9];
    const float* bo     = (const float*)d_in[10];
    const float* ln1_g  = (const float*)d_in[11];
    const float* ln1_b  = (const float*)d_in[12];
    const float* W1     = (const float*)d_in[13];
    const float* b1     = (const float*)d_in[14];
    const float* W2     = (const float*)d_in[15];
    const float* b2     = (const float*)d_in[16];
    const float* ln2_g  = (const float*)d_in[17];
    const float* ln2_b  = (const float*)d_in[18];
    const float* Wout1  = (const float*)d_in[19];
    const float* bout1  = (const float*)d_in[20];
    const float* Wout2  = (const float*)d_in[21];
    const float* bout2  = (const float*)d_in[22];
    const float* Wout3  = (const float*)d_in[23];
    const float* bout3  = (const float*)d_in[24];
    float* out = (float*)d_out;

    float *x, *y, *qe, *k, *v, *o, *tmp, *h1;
    cudaGetSymbolAddress((void**)&x,   g_x);
    cudaGetSymbolAddress((void**)&y,   g_y);
    cudaGetSymbolAddress((void**)&qe,  g_qe);
    cudaGetSymbolAddress((void**)&k,   g_k);
    cudaGetSymbolAddress((void**)&v,   g_v);
    cudaGetSymbolAddress((void**)&o,   g_o);
    cudaGetSymbolAddress((void**)&tmp, g_tmp);
    cudaGetSymbolAddress((void**)&h1,  g_h1);

    const int attn_smem = 3 * 64 * SPAD * (int)sizeof(float);
    cudaFuncSetAttribute(attn_kernel, cudaFuncAttributeMaxDynamicSharedMemorySize,
                         attn_smem);

    embed_kernel<<<NTOK, 128>>>(q_data, target, pe, q_emb, qa_emb, x, y, qe);

    for (int l = 0; l < LL; l++) {
        const float* Wk_l = Wk + (size_t)l * DD * DD;
        const float* bk_l = bk + (size_t)l * DD;
        const float* Wv_l = Wv + (size_t)l * DD * DD;
        const float* bv_l = bv + (size_t)l * DD;
        const float* Wo_l = Wo + (size_t)l * DD * DD;
        const float* bo_l = bo + (size_t)l * DD;
        const float* W1_l = W1 + (size_t)l * DD * DFFC;
        const float* b1_l = b1 + (size_t)l * DFFC;
        const float* W2_l = W2 + (size_t)l * DFFC * DD;
        const float* b2_l = b2 + (size_t)l * DD;

        tgemm<0, false, false><<<dim3(DD / 128, NTOK / 128), 256>>>(
            x, nullptr, Wk_l, bk_l, k, DD, DD);
        tgemm<0, false, false><<<dim3(DD / 128, NTOK / 128), 256>>>(
            y, nullptr, Wv_l, bv_l, v, DD, DD);
        attn_kernel<<<dim3(SS / 64, HH, BB), 256, attn_smem>>>(k, v, o);
        tgemm<0, false, false><<<dim3(DD / 128, NTOK / 128), 256>>>(
            o, nullptr, Wo_l, bo_l, tmp, DD, DD);
        add_ln_kernel<<<NTOK, 128>>>(x, tmp, ln1_g + (size_t)l * DD,
                                     ln1_b + (size_t)l * DD);
        for (int c = 0; c < NTOK / FFN_CHUNK; c++) {
            const float* xc = x   + (size_t)c * FFN_CHUNK * DD;
            float*       tc = tmp + (size_t)c * FFN_CHUNK * DD;
            tgemm<1, false, false><<<dim3(DFFC / 128, FFN_CHUNK / 128), 256>>>(
                xc, nullptr, W1_l, b1_l, h1, DFFC, DD);
            tgemm<0, false, false><<<dim3(DD / 128, FFN_CHUNK / 128), 256>>>(
                h1, nullptr, W2_l, b2_l, tc, DD, DFFC);
        }
        add_ln_kernel<<<NTOK, 128>>>(x, tmp, ln2_g + (size_t)l * DD,
                                     ln2_b + (size_t)l * DD);
    }

    // head
    tgemm<1, false, true><<<dim3(FC1C / 128, NTOK / 128), 256>>>(
        x, qe, Wout1, bout1, k, FC1C, 2 * DD);
    tgemm<1, false, false><<<dim3(FC2C / 128, NTOK / 128), 256>>>(
        k, nullptr, Wout2, bout2, v, FC2C, FC1C);
    tgemm<0, true, false><<<dim3((NSKC + 127) / 128, NTOK / 128), 256>>>(
        v, nullptr, Wout3, bout3, out, NSKC, FC2C);
}